// round 2
// baseline (speedup 1.0000x reference)
#include <cuda_runtime.h>

// Problem constants
#define BB 128
#define TT 2048
#define LL 8              // timesteps per chunk
#define CC (TT / LL)      // 256 chunks per batch
#define NM (BB * TT)      // 262144 matrices total
#define DT 0.02f

// Scratch: 32 floats per 4x4 complex matrix = [re[16], im[16]] = 8 float4 (128B)
__device__ __align__(128) float4 g_U[(size_t)NM * 8];        // 33.5 MB: all unitaries
__device__ __align__(128) float4 g_P[(size_t)BB * CC * 8];   // chunk products
__device__ __align__(128) float4 g_S[(size_t)BB * CC * 8];   // incoming state per chunk

// ---------------------------------------------------------------------------
// 4x4 complex matmul helpers (fully unrolled, 16 independent accumulators)
__device__ __forceinline__ void cmm(const float* __restrict__ xr, const float* __restrict__ xi,
                                    const float* __restrict__ yr, const float* __restrict__ yi,
                                    float* __restrict__ zr, float* __restrict__ zi) {
#pragma unroll
    for (int i = 0; i < 4; ++i) {
#pragma unroll
        for (int j = 0; j < 4; ++j) {
            float sr = 0.0f, si = 0.0f;
#pragma unroll
            for (int k = 0; k < 4; ++k) {
                float a = xr[i * 4 + k], bq = xi[i * 4 + k];
                float c = yr[k * 4 + j], d = yi[k * 4 + j];
                sr = fmaf(a, c, sr); sr = fmaf(-bq, d, sr);
                si = fmaf(a, d, si); si = fmaf(bq, c, si);
            }
            zr[i * 4 + j] = sr;
            zi[i * 4 + j] = si;
        }
    }
}

__device__ __forceinline__ void cmma(const float* __restrict__ xr, const float* __restrict__ xi,
                                     const float* __restrict__ yr, const float* __restrict__ yi,
                                     float* __restrict__ zr, float* __restrict__ zi) {
#pragma unroll
    for (int i = 0; i < 4; ++i) {
#pragma unroll
        for (int j = 0; j < 4; ++j) {
            float sr = zr[i * 4 + j], si = zi[i * 4 + j];
#pragma unroll
            for (int k = 0; k < 4; ++k) {
                float a = xr[i * 4 + k], bq = xi[i * 4 + k];
                float c = yr[k * 4 + j], d = yi[k * 4 + j];
                sr = fmaf(a, c, sr); sr = fmaf(-bq, d, sr);
                si = fmaf(a, d, si); si = fmaf(bq, c, si);
            }
            zr[i * 4 + j] = sr;
            zi[i * 4 + j] = si;
        }
    }
}

__device__ __forceinline__ void ld_mat(const float4* __restrict__ p, float* r, float* m) {
#pragma unroll
    for (int q = 0; q < 4; ++q) {
        float4 v = p[q];
        r[4 * q + 0] = v.x; r[4 * q + 1] = v.y; r[4 * q + 2] = v.z; r[4 * q + 3] = v.w;
    }
#pragma unroll
    for (int q = 0; q < 4; ++q) {
        float4 v = p[4 + q];
        m[4 * q + 0] = v.x; m[4 * q + 1] = v.y; m[4 * q + 2] = v.z; m[4 * q + 3] = v.w;
    }
}

__device__ __forceinline__ void st_mat(float4* __restrict__ p, const float* r, const float* m) {
#pragma unroll
    for (int q = 0; q < 4; ++q)
        p[q] = make_float4(r[4 * q + 0], r[4 * q + 1], r[4 * q + 2], r[4 * q + 3]);
#pragma unroll
    for (int q = 0; q < 4; ++q)
        p[4 + q] = make_float4(m[4 * q + 0], m[4 * q + 1], m[4 * q + 2], m[4 * q + 3]);
}

__device__ __forceinline__ void cp_mat(float* __restrict__ dr, float* __restrict__ di,
                                       const float* sr, const float* si) {
#pragma unroll
    for (int e = 0; e < 16; ++e) { dr[e] = sr[e]; di[e] = si[e]; }
}

// ---------------------------------------------------------------------------
// K0: expm (degree-6 Taylor, Paterson-Stockmeyer) + FUSED chunk product.
// Block = 128 threads = 128 consecutive matrices = 16 chunks.
__global__ void __launch_bounds__(128) k_expm(const float* __restrict__ hr_g,
                                              const float* __restrict__ hi_g) {
    int idx = blockIdx.x * 128 + threadIdx.x;   // = b*TT + t  (grid covers NM exactly)

    const float4* hr4 = reinterpret_cast<const float4*>(hr_g) + (size_t)idx * 4;
    const float4* hi4 = reinterpret_cast<const float4*>(hi_g) + (size_t)idx * 4;

    // A = -i*dt*(hr + i*hi) = dt*hi - i*dt*hr
    float ar[16], ai[16];
#pragma unroll
    for (int q = 0; q < 4; ++q) {
        float4 r = hr4[q], m = hi4[q];
        ar[4 * q + 0] =  DT * m.x; ar[4 * q + 1] =  DT * m.y;
        ar[4 * q + 2] =  DT * m.z; ar[4 * q + 3] =  DT * m.w;
        ai[4 * q + 0] = -DT * r.x; ai[4 * q + 1] = -DT * r.y;
        ai[4 * q + 2] = -DT * r.z; ai[4 * q + 3] = -DT * r.w;
    }

    float br[16], bi[16];               // A^2
    cmm(ar, ai, ar, ai, br, bi);
    float cr[16], ci[16];               // A^3
    cmm(br, bi, ar, ai, cr, ci);

    // M = I/6 + A/24 + A2/120 + A3/720
    float mr[16], mi[16];
#pragma unroll
    for (int e = 0; e < 16; ++e) {
        mr[e] = fmaf(1.0f / 24.0f, ar[e], fmaf(1.0f / 120.0f, br[e], (1.0f / 720.0f) * cr[e]));
        mi[e] = fmaf(1.0f / 24.0f, ai[e], fmaf(1.0f / 120.0f, bi[e], (1.0f / 720.0f) * ci[e]));
    }
    mr[0] += 1.0f / 6.0f; mr[5] += 1.0f / 6.0f; mr[10] += 1.0f / 6.0f; mr[15] += 1.0f / 6.0f;

    // E = I + A + A2/2  (into br/bi)
#pragma unroll
    for (int e = 0; e < 16; ++e) {
        br[e] = fmaf(0.5f, br[e], ar[e]);
        bi[e] = fmaf(0.5f, bi[e], ai[e]);
    }
    br[0] += 1.0f; br[5] += 1.0f; br[10] += 1.0f; br[15] += 1.0f;

    // E += A3 * M
    cmma(cr, ci, mr, mi, br, bi);

    st_mat(g_U + (size_t)idx * 8, br, bi);

    // ---- fused chunk product: 16 threads per block, reading just-written U
    // (__syncthreads orders the block's global writes before these reads)
    __syncthreads();
    if (threadIdx.x < 16) {
        int chunk = blockIdx.x * 16 + threadIdx.x;      // = b*CC + c
        size_t ub = (size_t)chunk * LL * 8;

        float pr[16], pi[16];
        ld_mat(g_U + ub, pr, pi);
        float ur[16], ui[16], tr[16], ti[16];
#pragma unroll
        for (int l = 1; l < LL; ++l) {
            ld_mat(g_U + ub + (size_t)l * 8, ur, ui);
            cmm(ur, ui, pr, pi, tr, ti);
            cp_mat(pr, pi, tr, ti);
        }
        st_mat(g_P + (size_t)chunk * 8, pr, pi);
    }
}

// ---------------------------------------------------------------------------
// K2: per-batch Kogge-Stone inclusive scan of chunk products, then emit
//     incoming state V_c = (P_{c-1}...P_0) * S0   (V_0 = S0)
#define SH_STRIDE 33   // pad to avoid bank conflicts

__global__ void __launch_bounds__(CC) k_scan(const float* __restrict__ s0r_g,
                                             const float* __restrict__ s0i_g) {
    __shared__ float sh[CC * SH_STRIDE];
    int b = blockIdx.x;
    int e = threadIdx.x;

    float pr[16], pi[16];
    ld_mat(g_P + ((size_t)b * CC + e) * 8, pr, pi);

    float qr[16], qi[16], tr[16], ti[16];
    for (int d = 1; d < CC; d <<= 1) {
        float* me = sh + e * SH_STRIDE;
#pragma unroll
        for (int k = 0; k < 16; ++k) { me[k] = pr[k]; me[16 + k] = pi[k]; }
        __syncthreads();
        if (e >= d) {
            const float* nb = sh + (e - d) * SH_STRIDE;
#pragma unroll
            for (int k = 0; k < 16; ++k) { qr[k] = nb[k]; qi[k] = nb[16 + k]; }
            cmm(pr, pi, qr, qi, tr, ti);   // newer-block * older-block
            cp_mat(pr, pi, tr, ti);
        }
        __syncthreads();
    }

    // publish inclusive prefixes; each thread fetches its left neighbor
    {
        float* me = sh + e * SH_STRIDE;
#pragma unroll
        for (int k = 0; k < 16; ++k) { me[k] = pr[k]; me[16 + k] = pi[k]; }
    }
    __syncthreads();

    float s0r[16], s0i[16];
    {
        const float4* r4 = reinterpret_cast<const float4*>(s0r_g) + (size_t)b * 4;
        const float4* i4 = reinterpret_cast<const float4*>(s0i_g) + (size_t)b * 4;
#pragma unroll
        for (int q = 0; q < 4; ++q) {
            float4 v = r4[q];
            s0r[4 * q + 0] = v.x; s0r[4 * q + 1] = v.y; s0r[4 * q + 2] = v.z; s0r[4 * q + 3] = v.w;
            float4 w = i4[q];
            s0i[4 * q + 0] = w.x; s0i[4 * q + 1] = w.y; s0i[4 * q + 2] = w.z; s0i[4 * q + 3] = w.w;
        }
    }

    float vr[16], vi[16];
    if (e == 0) {
        cp_mat(vr, vi, s0r, s0i);
    } else {
        const float* nb = sh + (e - 1) * SH_STRIDE;
#pragma unroll
        for (int k = 0; k < 16; ++k) { qr[k] = nb[k]; qi[k] = nb[16 + k]; }
        cmm(qr, qi, s0r, s0i, vr, vi);
    }
    st_mat(g_S + ((size_t)b * CC + e) * 8, vr, vi);
}

// ---------------------------------------------------------------------------
// K3: per-COLUMN apply. Thread = (chunk, column j). 131072 threads.
// Block = 128 threads = 32 chunks. Chunk's 8 unitaries staged in smem once
// (cooperative coalesced load), then each thread runs an 8-step U·s chain on
// its 4-complex column vector and streams results.
// smem layout: chunk cl occupies 65 float4 (260 floats: 256 data + 4 pad)
// -> bank group of float4 (l,q) is (4*cl + 4*q) % 32: conflict-free across the
//    8 chunks of a warp (4-lane groups broadcast).
#define CH_STRIDE4 65

__global__ void __launch_bounds__(128) k_apply(float* __restrict__ out) {
    __shared__ float4 sU[32 * CH_STRIDE4];

    int idx0 = blockIdx.x * 32;                 // first chunk of block
    int tid = threadIdx.x;

    // cooperative load: 32 chunks * 64 float4 each
#pragma unroll
    for (int k = tid; k < 32 * 64; k += 128) {
        int cl = k >> 6, w = k & 63;
        sU[cl * CH_STRIDE4 + w] = g_U[((size_t)(idx0 + cl)) * 64 + w];
    }
    __syncthreads();

    int cl = tid >> 2;
    int j  = tid & 3;
    int idx = idx0 + cl;                        // = b*CC + c
    int b = idx >> 8;                           // /CC
    int c = idx & (CC - 1);

    // initial column j of incoming state
    float sr[4], si[4];
    {
        const float* Sp = reinterpret_cast<const float*>(g_S) + (size_t)idx * 32;
#pragma unroll
        for (int i = 0; i < 4; ++i) { sr[i] = Sp[i * 4 + j]; si[i] = Sp[16 + i * 4 + j]; }
    }

    const float4* Ub = sU + cl * CH_STRIDE4;
    const size_t imag_off = (size_t)TT * BB * 16;

#pragma unroll
    for (int l = 0; l < LL; ++l) {
        float tr[4], ti[4];
#pragma unroll
        for (int i = 0; i < 4; ++i) {
            float4 urv = Ub[l * 8 + i];         // row i, real
            float4 uiv = Ub[l * 8 + 4 + i];     // row i, imag
            float xr = 0.0f, xi = 0.0f;
            xr = fmaf(urv.x, sr[0], xr); xr = fmaf(-uiv.x, si[0], xr);
            xi = fmaf(urv.x, si[0], xi); xi = fmaf( uiv.x, sr[0], xi);
            xr = fmaf(urv.y, sr[1], xr); xr = fmaf(-uiv.y, si[1], xr);
            xi = fmaf(urv.y, si[1], xi); xi = fmaf( uiv.y, sr[1], xi);
            xr = fmaf(urv.z, sr[2], xr); xr = fmaf(-uiv.z, si[2], xr);
            xi = fmaf(urv.z, si[2], xi); xi = fmaf( uiv.z, sr[2], xi);
            xr = fmaf(urv.w, sr[3], xr); xr = fmaf(-uiv.w, si[3], xr);
            xi = fmaf(urv.w, si[3], xi); xi = fmaf( uiv.w, sr[3], xi);
            tr[i] = xr; ti[i] = xi;
        }
#pragma unroll
        for (int i = 0; i < 4; ++i) { sr[i] = tr[i]; si[i] = ti[i]; }

        size_t t = (size_t)c * LL + l;
        size_t base = (t * BB + b) * 16 + j;
#pragma unroll
        for (int i = 0; i < 4; ++i) {
            out[base + i * 4]            = sr[i];
            out[imag_off + base + i * 4] = si[i];
        }
    }
}

// ---------------------------------------------------------------------------
extern "C" void kernel_launch(void* const* d_in, const int* in_sizes, int n_in,
                              void* d_out, int out_size) {
    const float* h_real = (const float*)d_in[0];
    const float* h_imag = (const float*)d_in[1];
    const float* s_real = (const float*)d_in[2];
    const float* s_imag = (const float*)d_in[3];
    float* out = (float*)d_out;

    k_expm<<<NM / 128, 128>>>(h_real, h_imag);
    k_scan<<<BB, CC>>>(s_real, s_imag);
    k_apply<<<(BB * CC * 4) / 128, 128>>>(out);
}

// round 3
// speedup vs baseline: 1.0835x; 1.0835x over previous
#include <cuda_runtime.h>

// Problem constants
#define BB 128
#define TT 2048
#define LL 8              // timesteps per chunk
#define CC (TT / LL)      // 256 chunks per batch
#define NM (BB * TT)      // 262144 matrices total
#define DT 0.02f

// Scratch: 32 floats per 4x4 complex matrix = [re[16], im[16]] = 8 float4 (128B)
__device__ __align__(128) float4 g_U[(size_t)NM * 8];        // 33.5 MB: all unitaries
__device__ __align__(128) float4 g_P[(size_t)BB * CC * 8];   // chunk products
__device__ __align__(128) float4 g_S[(size_t)BB * CC * 8];   // incoming state per chunk

// ---------------------------------------------------------------------------
// 4x4 complex matmul: z = x * y (no aliasing)
__device__ __forceinline__ void cmm(const float* __restrict__ xr, const float* __restrict__ xi,
                                    const float* __restrict__ yr, const float* __restrict__ yi,
                                    float* __restrict__ zr, float* __restrict__ zi) {
#pragma unroll
    for (int i = 0; i < 4; ++i) {
#pragma unroll
        for (int j = 0; j < 4; ++j) {
            float sr = 0.0f, si = 0.0f;
#pragma unroll
            for (int k = 0; k < 4; ++k) {
                float a = xr[i * 4 + k], bq = xi[i * 4 + k];
                float c = yr[k * 4 + j], d = yi[k * 4 + j];
                sr = fmaf(a, c, sr); sr = fmaf(-bq, d, sr);
                si = fmaf(a, d, si); si = fmaf(bq, c, si);
            }
            zr[i * 4 + j] = sr;
            zi[i * 4 + j] = si;
        }
    }
}

// z += x * y
__device__ __forceinline__ void cmma(const float* __restrict__ xr, const float* __restrict__ xi,
                                     const float* __restrict__ yr, const float* __restrict__ yi,
                                     float* __restrict__ zr, float* __restrict__ zi) {
#pragma unroll
    for (int i = 0; i < 4; ++i) {
#pragma unroll
        for (int j = 0; j < 4; ++j) {
            float sr = zr[i * 4 + j], si = zi[i * 4 + j];
#pragma unroll
            for (int k = 0; k < 4; ++k) {
                float a = xr[i * 4 + k], bq = xi[i * 4 + k];
                float c = yr[k * 4 + j], d = yi[k * 4 + j];
                sr = fmaf(a, c, sr); sr = fmaf(-bq, d, sr);
                si = fmaf(a, d, si); si = fmaf(bq, c, si);
            }
            zr[i * 4 + j] = sr;
            zi[i * 4 + j] = si;
        }
    }
}

__device__ __forceinline__ void ld_mat(const float4* __restrict__ p, float* r, float* m) {
#pragma unroll
    for (int q = 0; q < 4; ++q) {
        float4 v = p[q];
        r[4 * q + 0] = v.x; r[4 * q + 1] = v.y; r[4 * q + 2] = v.z; r[4 * q + 3] = v.w;
    }
#pragma unroll
    for (int q = 0; q < 4; ++q) {
        float4 v = p[4 + q];
        m[4 * q + 0] = v.x; m[4 * q + 1] = v.y; m[4 * q + 2] = v.z; m[4 * q + 3] = v.w;
    }
}

__device__ __forceinline__ void st_mat(float4* __restrict__ p, const float* r, const float* m) {
#pragma unroll
    for (int q = 0; q < 4; ++q)
        p[q] = make_float4(r[4 * q + 0], r[4 * q + 1], r[4 * q + 2], r[4 * q + 3]);
#pragma unroll
    for (int q = 0; q < 4; ++q)
        p[4 + q] = make_float4(m[4 * q + 0], m[4 * q + 1], m[4 * q + 2], m[4 * q + 3]);
}

__device__ __forceinline__ void cp_mat(float* __restrict__ dr, float* __restrict__ di,
                                       const float* sr, const float* si) {
#pragma unroll
    for (int e = 0; e < 16; ++e) { dr[e] = sr[e]; di[e] = si[e]; }
}

// ---------------------------------------------------------------------------
// K0: one thread per matrix: U = expm(-i*dt*H), degree-6 Taylor (Paterson-
// Stockmeyer), register-liveness-minimized: after A^3, fold E and M in place
// so peak live = A3 + M + E = 96 floats (not 160).
__global__ void __launch_bounds__(128) k_expm(const float* __restrict__ hr_g,
                                              const float* __restrict__ hi_g) {
    int idx = blockIdx.x * 128 + threadIdx.x;   // grid covers NM exactly

    const float4* hr4 = reinterpret_cast<const float4*>(hr_g) + (size_t)idx * 4;
    const float4* hi4 = reinterpret_cast<const float4*>(hi_g) + (size_t)idx * 4;

    // A = -i*dt*(hr + i*hi) = dt*hi - i*dt*hr
    float ar[16], ai[16];
#pragma unroll
    for (int q = 0; q < 4; ++q) {
        float4 r = hr4[q], m = hi4[q];
        ar[4 * q + 0] =  DT * m.x; ar[4 * q + 1] =  DT * m.y;
        ar[4 * q + 2] =  DT * m.z; ar[4 * q + 3] =  DT * m.w;
        ai[4 * q + 0] = -DT * r.x; ai[4 * q + 1] = -DT * r.y;
        ai[4 * q + 2] = -DT * r.z; ai[4 * q + 3] = -DT * r.w;
    }

    float br[16], bi[16];               // A^2
    cmm(ar, ai, ar, ai, br, bi);
    float cr[16], ci[16];               // A^3
    cmm(br, bi, ar, ai, cr, ci);

    // In-place fold:
    //   E (into ar/ai) = A + A2/2          (+ I on diag below)
    //   M (into br/bi) = A/24 + A2/120 + A3/720   (+ I/6 on diag below)
#pragma unroll
    for (int e = 0; e < 16; ++e) {
        float tr_ = ar[e], ti_ = ai[e];
        ar[e] = fmaf(0.5f, br[e], tr_);
        ai[e] = fmaf(0.5f, bi[e], ti_);
        br[e] = fmaf(1.0f / 24.0f, tr_, fmaf(1.0f / 120.0f, br[e], (1.0f / 720.0f) * cr[e]));
        bi[e] = fmaf(1.0f / 24.0f, ti_, fmaf(1.0f / 120.0f, bi[e], (1.0f / 720.0f) * ci[e]));
    }
    ar[0] += 1.0f; ar[5] += 1.0f; ar[10] += 1.0f; ar[15] += 1.0f;
    br[0] += 1.0f / 6.0f; br[5] += 1.0f / 6.0f; br[10] += 1.0f / 6.0f; br[15] += 1.0f / 6.0f;

    // E += A3 * M
    cmma(cr, ci, br, bi, ar, ai);

    st_mat(g_U + (size_t)idx * 8, ar, ai);
}

// ---------------------------------------------------------------------------
// Shared smem staging geometry for k_chunk / k_apply:
// block = 128 threads = 32 chunks x 4 columns; chunk cl occupies 65 float4
// (4-float pad kills bank conflicts; 4-lane groups broadcast).
#define CH_STRIDE4 65

__device__ __forceinline__ void stage_chunks(float4* sU, int idx0, int tid) {
#pragma unroll
    for (int k = tid; k < 32 * 64; k += 128) {
        int cl = k >> 6, w = k & 63;
        sU[cl * CH_STRIDE4 + w] = g_U[((size_t)(idx0 + cl)) * 64 + w];
    }
}

// one step: (sr,si) <- U_l * (sr,si), U_l from smem
__device__ __forceinline__ void matvec_step(const float4* __restrict__ Ub, int l,
                                            float* __restrict__ sr, float* __restrict__ si) {
    float tr[4], ti[4];
#pragma unroll
    for (int i = 0; i < 4; ++i) {
        float4 urv = Ub[l * 8 + i];         // row i, real
        float4 uiv = Ub[l * 8 + 4 + i];     // row i, imag
        float xr = 0.0f, xi = 0.0f;
        xr = fmaf(urv.x, sr[0], xr); xr = fmaf(-uiv.x, si[0], xr);
        xi = fmaf(urv.x, si[0], xi); xi = fmaf( uiv.x, sr[0], xi);
        xr = fmaf(urv.y, sr[1], xr); xr = fmaf(-uiv.y, si[1], xr);
        xi = fmaf(urv.y, si[1], xi); xi = fmaf( uiv.y, sr[1], xi);
        xr = fmaf(urv.z, sr[2], xr); xr = fmaf(-uiv.z, si[2], xr);
        xi = fmaf(urv.z, si[2], xi); xi = fmaf( uiv.z, sr[2], xi);
        xr = fmaf(urv.w, sr[3], xr); xr = fmaf(-uiv.w, si[3], xr);
        xi = fmaf(urv.w, si[3], xi); xi = fmaf( uiv.w, sr[3], xi);
        tr[i] = xr; ti[i] = xi;
    }
#pragma unroll
    for (int i = 0; i < 4; ++i) { sr[i] = tr[i]; si[i] = ti[i]; }
}

// ---------------------------------------------------------------------------
// K1: per-column chunk product. Thread = (chunk, column j): P e_j computed as
// U7(...(U0 e_j)) — 8 mat-vecs. 131072 threads.
__global__ void __launch_bounds__(128) k_chunk() {
    __shared__ float4 sU[32 * CH_STRIDE4];
    int idx0 = blockIdx.x * 32;
    int tid = threadIdx.x;
    stage_chunks(sU, idx0, tid);
    __syncthreads();

    int cl = tid >> 2, j = tid & 3;
    int idx = idx0 + cl;

    float sr[4] = {0, 0, 0, 0}, si[4] = {0, 0, 0, 0};
    sr[j] = 1.0f;

    const float4* Ub = sU + cl * CH_STRIDE4;
#pragma unroll
    for (int l = 0; l < LL; ++l) matvec_step(Ub, l, sr, si);

    float* Pp = reinterpret_cast<float*>(g_P) + (size_t)idx * 32;
#pragma unroll
    for (int i = 0; i < 4; ++i) { Pp[i * 4 + j] = sr[i]; Pp[16 + i * 4 + j] = si[i]; }
}

// ---------------------------------------------------------------------------
// K2: per-batch Kogge-Stone inclusive scan of chunk products, then emit
//     incoming state V_c = (P_{c-1}...P_0) * S0   (V_0 = S0)
#define SH_STRIDE 33

__global__ void __launch_bounds__(CC) k_scan(const float* __restrict__ s0r_g,
                                             const float* __restrict__ s0i_g) {
    __shared__ float sh[CC * SH_STRIDE];
    int b = blockIdx.x;
    int e = threadIdx.x;

    float pr[16], pi[16];
    ld_mat(g_P + ((size_t)b * CC + e) * 8, pr, pi);

    float qr[16], qi[16], tr[16], ti[16];
    for (int d = 1; d < CC; d <<= 1) {
        float* me = sh + e * SH_STRIDE;
#pragma unroll
        for (int k = 0; k < 16; ++k) { me[k] = pr[k]; me[16 + k] = pi[k]; }
        __syncthreads();
        if (e >= d) {
            const float* nb = sh + (e - d) * SH_STRIDE;
#pragma unroll
            for (int k = 0; k < 16; ++k) { qr[k] = nb[k]; qi[k] = nb[16 + k]; }
            cmm(pr, pi, qr, qi, tr, ti);   // newer-block * older-block
            cp_mat(pr, pi, tr, ti);
        }
        __syncthreads();
    }

    {
        float* me = sh + e * SH_STRIDE;
#pragma unroll
        for (int k = 0; k < 16; ++k) { me[k] = pr[k]; me[16 + k] = pi[k]; }
    }
    __syncthreads();

    float s0r[16], s0i[16];
    {
        const float4* r4 = reinterpret_cast<const float4*>(s0r_g) + (size_t)b * 4;
        const float4* i4 = reinterpret_cast<const float4*>(s0i_g) + (size_t)b * 4;
#pragma unroll
        for (int q = 0; q < 4; ++q) {
            float4 v = r4[q];
            s0r[4 * q + 0] = v.x; s0r[4 * q + 1] = v.y; s0r[4 * q + 2] = v.z; s0r[4 * q + 3] = v.w;
            float4 w = i4[q];
            s0i[4 * q + 0] = w.x; s0i[4 * q + 1] = w.y; s0i[4 * q + 2] = w.z; s0i[4 * q + 3] = w.w;
        }
    }

    float vr[16], vi[16];
    if (e == 0) {
        cp_mat(vr, vi, s0r, s0i);
    } else {
        const float* nb = sh + (e - 1) * SH_STRIDE;
#pragma unroll
        for (int k = 0; k < 16; ++k) { qr[k] = nb[k]; qi[k] = nb[16 + k]; }
        cmm(qr, qi, s0r, s0i, vr, vi);
    }
    st_mat(g_S + ((size_t)b * CC + e) * 8, vr, vi);
}

// ---------------------------------------------------------------------------
// K3: per-column apply. Thread = (chunk, column j); replays 8 steps from the
// incoming state's column and streams outputs. Output: [2, T, B, 4, 4] f32.
__global__ void __launch_bounds__(128) k_apply(float* __restrict__ out) {
    __shared__ float4 sU[32 * CH_STRIDE4];
    int idx0 = blockIdx.x * 32;
    int tid = threadIdx.x;
    stage_chunks(sU, idx0, tid);
    __syncthreads();

    int cl = tid >> 2, j = tid & 3;
    int idx = idx0 + cl;                        // = b*CC + c
    int b = idx >> 8;                           // /CC
    int c = idx & (CC - 1);

    float sr[4], si[4];
    {
        const float* Sp = reinterpret_cast<const float*>(g_S) + (size_t)idx * 32;
#pragma unroll
        for (int i = 0; i < 4; ++i) { sr[i] = Sp[i * 4 + j]; si[i] = Sp[16 + i * 4 + j]; }
    }

    const float4* Ub = sU + cl * CH_STRIDE4;
    const size_t imag_off = (size_t)TT * BB * 16;

#pragma unroll
    for (int l = 0; l < LL; ++l) {
        matvec_step(Ub, l, sr, si);

        size_t t = (size_t)c * LL + l;
        size_t base = (t * BB + b) * 16 + j;
#pragma unroll
        for (int i = 0; i < 4; ++i) {
            out[base + i * 4]            = sr[i];
            out[imag_off + base + i * 4] = si[i];
        }
    }
}

// ---------------------------------------------------------------------------
extern "C" void kernel_launch(void* const* d_in, const int* in_sizes, int n_in,
                              void* d_out, int out_size) {
    const float* h_real = (const float*)d_in[0];
    const float* h_imag = (const float*)d_in[1];
    const float* s_real = (const float*)d_in[2];
    const float* s_imag = (const float*)d_in[3];
    float* out = (float*)d_out;

    k_expm<<<NM / 128, 128>>>(h_real, h_imag);
    k_chunk<<<(BB * CC) / 32, 128>>>();
    k_scan<<<BB, CC>>>(s_real, s_imag);
    k_apply<<<(BB * CC) / 32, 128>>>(out);
}

// round 4
// speedup vs baseline: 1.1887x; 1.0971x over previous
#include <cuda_runtime.h>

// Problem constants
#define BB 128
#define TT 2048
#define LL 8              // timesteps per chunk
#define CC (TT / LL)      // 256 chunks per batch
#define NM (BB * TT)      // 262144 matrices total
#define DT 0.02f

// Scratch: 32 floats per 4x4 complex matrix = [re[16], im[16]] = 8 float4 (128B)
__device__ __align__(128) float4 g_U[(size_t)NM * 8];        // 33.5 MB: all unitaries
__device__ __align__(128) float4 g_P[(size_t)BB * CC * 8];   // chunk products
__device__ __align__(128) float4 g_S[(size_t)BB * CC * 8];   // incoming state per chunk

// ---------------------------------------------------------------------------
// complex-scalar (a+bi) times complex row (cr+i*ci), accumulated into (ar,ai)
__device__ __forceinline__ void cax4(float a, float b, float4 cr, float4 ci,
                                     float4& accr, float4& acci) {
    accr.x = fmaf(a, cr.x, fmaf(-b, ci.x, accr.x));
    acci.x = fmaf(a, ci.x, fmaf( b, cr.x, acci.x));
    accr.y = fmaf(a, cr.y, fmaf(-b, ci.y, accr.y));
    acci.y = fmaf(a, ci.y, fmaf( b, cr.y, acci.y));
    accr.z = fmaf(a, cr.z, fmaf(-b, ci.z, accr.z));
    acci.z = fmaf(a, ci.z, fmaf( b, cr.z, acci.z));
    accr.w = fmaf(a, cr.w, fmaf(-b, ci.w, accr.w));
    acci.w = fmaf(a, ci.w, fmaf( b, cr.w, acci.w));
}

// 4x4 complex matmul: z = x * y (no aliasing), scalar-array form
__device__ __forceinline__ void cmm(const float* __restrict__ xr, const float* __restrict__ xi,
                                    const float* __restrict__ yr, const float* __restrict__ yi,
                                    float* __restrict__ zr, float* __restrict__ zi) {
#pragma unroll
    for (int i = 0; i < 4; ++i) {
#pragma unroll
        for (int j = 0; j < 4; ++j) {
            float sr = 0.0f, si = 0.0f;
#pragma unroll
            for (int k = 0; k < 4; ++k) {
                float a = xr[i * 4 + k], bq = xi[i * 4 + k];
                float c = yr[k * 4 + j], d = yi[k * 4 + j];
                sr = fmaf(a, c, sr); sr = fmaf(-bq, d, sr);
                si = fmaf(a, d, si); si = fmaf(bq, c, si);
            }
            zr[i * 4 + j] = sr;
            zi[i * 4 + j] = si;
        }
    }
}

// z += x * y
__device__ __forceinline__ void cmma(const float* __restrict__ xr, const float* __restrict__ xi,
                                     const float* __restrict__ yr, const float* __restrict__ yi,
                                     float* __restrict__ zr, float* __restrict__ zi) {
#pragma unroll
    for (int i = 0; i < 4; ++i) {
#pragma unroll
        for (int j = 0; j < 4; ++j) {
            float sr = zr[i * 4 + j], si = zi[i * 4 + j];
#pragma unroll
            for (int k = 0; k < 4; ++k) {
                float a = xr[i * 4 + k], bq = xi[i * 4 + k];
                float c = yr[k * 4 + j], d = yi[k * 4 + j];
                sr = fmaf(a, c, sr); sr = fmaf(-bq, d, sr);
                si = fmaf(a, d, si); si = fmaf(bq, c, si);
            }
            zr[i * 4 + j] = sr;
            zi[i * 4 + j] = si;
        }
    }
}

__device__ __forceinline__ void st_mat(float4* __restrict__ p, const float* r, const float* m) {
#pragma unroll
    for (int q = 0; q < 4; ++q)
        p[q] = make_float4(r[4 * q + 0], r[4 * q + 1], r[4 * q + 2], r[4 * q + 3]);
#pragma unroll
    for (int q = 0; q < 4; ++q)
        p[4 + q] = make_float4(m[4 * q + 0], m[4 * q + 1], m[4 * q + 2], m[4 * q + 3]);
}

// ---------------------------------------------------------------------------
// K0: U = expm(-i*dt*H), degree-4 Taylor, 2 matmuls:
//   E = I + A + A^2 * (I/2 + A/6 + A^2/24)
// Truncation <= ||A||^5/113 <= 7e-7/step (||A|| <= ~0.15) — accumulated
// worst-case 1e-4, far under the 1e-3 threshold.
__global__ void __launch_bounds__(128) k_expm(const float* __restrict__ hr_g,
                                              const float* __restrict__ hi_g) {
    int idx = blockIdx.x * 128 + threadIdx.x;   // grid covers NM exactly

    const float4* hr4 = reinterpret_cast<const float4*>(hr_g) + (size_t)idx * 4;
    const float4* hi4 = reinterpret_cast<const float4*>(hi_g) + (size_t)idx * 4;

    // A = -i*dt*(hr + i*hi) = dt*hi - i*dt*hr
    float ar[16], ai[16];
#pragma unroll
    for (int q = 0; q < 4; ++q) {
        float4 r = hr4[q], m = hi4[q];
        ar[4 * q + 0] =  DT * m.x; ar[4 * q + 1] =  DT * m.y;
        ar[4 * q + 2] =  DT * m.z; ar[4 * q + 3] =  DT * m.w;
        ai[4 * q + 0] = -DT * r.x; ai[4 * q + 1] = -DT * r.y;
        ai[4 * q + 2] = -DT * r.z; ai[4 * q + 3] = -DT * r.w;
    }

    float br[16], bi[16];               // A^2
    cmm(ar, ai, ar, ai, br, bi);

    // M = I/2 + A/6 + A2/24
    float mr[16], mi[16];
#pragma unroll
    for (int e = 0; e < 16; ++e) {
        mr[e] = fmaf(1.0f / 6.0f, ar[e], (1.0f / 24.0f) * br[e]);
        mi[e] = fmaf(1.0f / 6.0f, ai[e], (1.0f / 24.0f) * bi[e]);
    }
    mr[0] += 0.5f; mr[5] += 0.5f; mr[10] += 0.5f; mr[15] += 0.5f;

    // E = A + A2*M  (into ar/ai), then +I
    cmma(br, bi, mr, mi, ar, ai);
    ar[0] += 1.0f; ar[5] += 1.0f; ar[10] += 1.0f; ar[15] += 1.0f;

    st_mat(g_U + (size_t)idx * 8, ar, ai);
}

// ---------------------------------------------------------------------------
// K1: per-column chunk product (sync-free: column update needs full U but
// only own column of the accumulator). Thread = (chunk, column j).
#define CH_STRIDE4 65

__global__ void __launch_bounds__(128) k_chunk() {
    __shared__ float4 sU[32 * CH_STRIDE4];
    int idx0 = blockIdx.x * 32;
    int tid = threadIdx.x;
#pragma unroll
    for (int k = tid; k < 32 * 64; k += 128) {
        int cl = k >> 6, w = k & 63;
        sU[cl * CH_STRIDE4 + w] = g_U[((size_t)(idx0 + cl)) * 64 + w];
    }
    __syncthreads();

    int cl = tid >> 2, j = tid & 3;
    int idx = idx0 + cl;

    float sr[4] = {0, 0, 0, 0}, si[4] = {0, 0, 0, 0};
    sr[j] = 1.0f;

    const float4* Ub = sU + cl * CH_STRIDE4;
#pragma unroll
    for (int l = 0; l < LL; ++l) {
        float tr[4], ti[4];
#pragma unroll
        for (int i = 0; i < 4; ++i) {
            float4 urv = Ub[l * 8 + i];
            float4 uiv = Ub[l * 8 + 4 + i];
            float xr = 0.0f, xi = 0.0f;
            xr = fmaf(urv.x, sr[0], xr); xr = fmaf(-uiv.x, si[0], xr);
            xi = fmaf(urv.x, si[0], xi); xi = fmaf( uiv.x, sr[0], xi);
            xr = fmaf(urv.y, sr[1], xr); xr = fmaf(-uiv.y, si[1], xr);
            xi = fmaf(urv.y, si[1], xi); xi = fmaf( uiv.y, sr[1], xi);
            xr = fmaf(urv.z, sr[2], xr); xr = fmaf(-uiv.z, si[2], xr);
            xi = fmaf(urv.z, si[2], xi); xi = fmaf( uiv.z, sr[2], xi);
            xr = fmaf(urv.w, sr[3], xr); xr = fmaf(-uiv.w, si[3], xr);
            xi = fmaf(urv.w, si[3], xi); xi = fmaf( uiv.w, sr[3], xi);
            tr[i] = xr; ti[i] = xi;
        }
#pragma unroll
        for (int i = 0; i < 4; ++i) { sr[i] = tr[i]; si[i] = ti[i]; }
    }

    float* Pp = reinterpret_cast<float*>(g_P) + (size_t)idx * 32;
#pragma unroll
    for (int i = 0; i < 4; ++i) { Pp[i * 4 + j] = sr[i]; Pp[16 + i * 4 + j] = si[i]; }
}

// ---------------------------------------------------------------------------
// K2: row-parallel per-batch Kogge-Stone scan. 1024 threads = 256 chunks x 4
// rows. Thread holds row i of its chunk's running product; each round it
// multiplies its row into the left neighbor's full matrix (read from smem).
// Then V_e = Prefix_{e-1} * S0 (V_0 = S0), rows written coalesced to g_S.
__global__ void __launch_bounds__(1024) k_scan(const float* __restrict__ s0r_g,
                                               const float* __restrict__ s0i_g) {
    __shared__ float4 sh[CC * 12];   // 48KB: per chunk 8 data quads + 4 pad
    int b = blockIdx.x;
    int tid = threadIdx.x;
    int e = tid >> 2, i = tid & 3;

    const float4* Pg = g_P + ((size_t)b * CC + e) * 8;
    float4 pr = Pg[i];        // row i of P_e, real
    float4 pim = Pg[4 + i];   // row i, imag

#pragma unroll
    for (int d = 1; d < CC; d <<= 1) {
        sh[e * 12 + i] = pr;
        sh[e * 12 + 4 + i] = pim;
        __syncthreads();
        if (e >= d) {
            const float4* nb = sh + (e - d) * 12;
            float4 l0r = nb[0], l1r = nb[1], l2r = nb[2], l3r = nb[3];
            float4 l0i = nb[4], l1i = nb[5], l2i = nb[6], l3i = nb[7];
            float4 nr = make_float4(0, 0, 0, 0), ni = make_float4(0, 0, 0, 0);
            cax4(pr.x, pim.x, l0r, l0i, nr, ni);
            cax4(pr.y, pim.y, l1r, l1i, nr, ni);
            cax4(pr.z, pim.z, l2r, l2i, nr, ni);
            cax4(pr.w, pim.w, l3r, l3i, nr, ni);
            pr = nr; pim = ni;
        }
        __syncthreads();
    }

    // publish inclusive prefixes
    sh[e * 12 + i] = pr;
    sh[e * 12 + 4 + i] = pim;
    __syncthreads();

    // S0 rows (broadcast loads, L2/L1 cached)
    const float4* r4 = reinterpret_cast<const float4*>(s0r_g) + (size_t)b * 4;
    const float4* i4 = reinterpret_cast<const float4*>(s0i_g) + (size_t)b * 4;
    float4 s0r0 = r4[0], s0r1 = r4[1], s0r2 = r4[2], s0r3 = r4[3];
    float4 s0i0 = i4[0], s0i1 = i4[1], s0i2 = i4[2], s0i3 = i4[3];

    float4 vr, vi;
    if (e == 0) {
        vr = (i == 0) ? s0r0 : (i == 1) ? s0r1 : (i == 2) ? s0r2 : s0r3;
        vi = (i == 0) ? s0i0 : (i == 1) ? s0i1 : (i == 2) ? s0i2 : s0i3;
    } else {
        float4 qr = sh[(e - 1) * 12 + i];      // row i of Prefix_{e-1}
        float4 qi = sh[(e - 1) * 12 + 4 + i];
        vr = make_float4(0, 0, 0, 0); vi = make_float4(0, 0, 0, 0);
        cax4(qr.x, qi.x, s0r0, s0i0, vr, vi);
        cax4(qr.y, qi.y, s0r1, s0i1, vr, vi);
        cax4(qr.z, qi.z, s0r2, s0i2, vr, vi);
        cax4(qr.w, qi.w, s0r3, s0i3, vr, vi);
    }
    float4* Sg = g_S + ((size_t)b * CC + e) * 8;
    Sg[i] = vr;
    Sg[4 + i] = vi;
}

// ---------------------------------------------------------------------------
// K3: ROW-parallel apply. Thread = (chunk, row i). State lives in smem
// (double-buffered); each step the thread computes new row i from the full
// old state and stores it as two coalesced STG.128.
#define USTR4 68   // quad-stride for sU: 68 % 8 == 4 -> conflict-free row reads

__global__ void __launch_bounds__(128) k_apply(float* __restrict__ out) {
    __shared__ float4 sU[32 * USTR4];        // 34816 B
    __shared__ float4 sS[2][32 * 12];        // 12288 B, double-buffered state

    int idx0 = blockIdx.x * 32;
    int tid = threadIdx.x;
#pragma unroll
    for (int k = tid; k < 32 * 64; k += 128) {
        int cl = k >> 6, w = k & 63;
        sU[cl * USTR4 + w] = g_U[((size_t)(idx0 + cl)) * 64 + w];
    }

    int cl = tid >> 2, i = tid & 3;
    int idx = idx0 + cl;                     // = b*CC + c
    int b = idx >> 8;
    int c = idx & (CC - 1);

    {   // stage incoming state rows (fully coalesced float4 loads)
        const float4* Sg = g_S + (size_t)idx * 8;
        sS[0][cl * 12 + i] = Sg[i];
        sS[0][cl * 12 + 4 + i] = Sg[4 + i];
    }
    __syncthreads();

    const float4* Ub = sU + cl * USTR4;
    const size_t imag_off = (size_t)TT * BB * 16;
    float* ob = out + (((size_t)c * LL) * BB + b) * 16 + i * 4;

#pragma unroll
    for (int l = 0; l < LL; ++l) {
        const int cur = l & 1;
        float4 s0r = sS[cur][cl * 12 + 0];
        float4 s1r = sS[cur][cl * 12 + 1];
        float4 s2r = sS[cur][cl * 12 + 2];
        float4 s3r = sS[cur][cl * 12 + 3];
        float4 s0i = sS[cur][cl * 12 + 4];
        float4 s1i = sS[cur][cl * 12 + 5];
        float4 s2i = sS[cur][cl * 12 + 6];
        float4 s3i = sS[cur][cl * 12 + 7];

        float4 ur = Ub[l * 8 + i];       // U[i, 0..3] real
        float4 ui = Ub[l * 8 + 4 + i];   // U[i, 0..3] imag

        float4 nr = make_float4(0, 0, 0, 0), ni = make_float4(0, 0, 0, 0);
        cax4(ur.x, ui.x, s0r, s0i, nr, ni);
        cax4(ur.y, ui.y, s1r, s1i, nr, ni);
        cax4(ur.z, ui.z, s2r, s2i, nr, ni);
        cax4(ur.w, ui.w, s3r, s3i, nr, ni);

        if (l < LL - 1) {
            sS[cur ^ 1][cl * 12 + i] = nr;
            sS[cur ^ 1][cl * 12 + 4 + i] = ni;
        }

        float* op = ob + (size_t)l * BB * 16;
        *reinterpret_cast<float4*>(op) = nr;
        *reinterpret_cast<float4*>(op + imag_off) = ni;

        __syncwarp();
    }
}

// ---------------------------------------------------------------------------
extern "C" void kernel_launch(void* const* d_in, const int* in_sizes, int n_in,
                              void* d_out, int out_size) {
    const float* h_real = (const float*)d_in[0];
    const float* h_imag = (const float*)d_in[1];
    const float* s_real = (const float*)d_in[2];
    const float* s_imag = (const float*)d_in[3];
    float* out = (float*)d_out;

    k_expm<<<NM / 128, 128>>>(h_real, h_imag);
    k_chunk<<<(BB * CC) / 32, 128>>>();
    k_scan<<<BB, CC * 4>>>(s_real, s_imag);
    k_apply<<<(BB * CC) / 32, 128>>>(out);
}

// round 5
// speedup vs baseline: 1.2296x; 1.0344x over previous
#include <cuda_runtime.h>

// Problem constants
#define BB 128
#define TT 2048
#define LL 8              // timesteps per chunk
#define CC (TT / LL)      // 256 chunks per batch
#define NM (BB * TT)      // 262144 matrices total
#define DT 0.02f

// Scratch: 32 floats per 4x4 complex matrix = [re[16], im[16]] = 8 float4 (128B)
__device__ __align__(128) float4 g_U[(size_t)NM * 8];        // 33.5 MB: all unitaries
__device__ __align__(128) float4 g_P[(size_t)BB * CC * 8];   // chunk products
__device__ __align__(128) float4 g_S[(size_t)BB * CC * 8];   // incoming state per chunk

// ---------------------------------------------------------------------------
// Packed f32x2 primitives (FFMA2 — only reachable via PTX)
typedef unsigned long long u64p;

__device__ __forceinline__ u64p pk2(float x, float y) {
    u64p r; asm("mov.b64 %0, {%1, %2};" : "=l"(r) : "f"(x), "f"(y)); return r;
}
__device__ __forceinline__ void upk2(u64p v, float& x, float& y) {
    asm("mov.b64 {%0, %1}, %2;" : "=f"(x), "=f"(y) : "l"(v));
}
__device__ __forceinline__ u64p psplat(float a) { return pk2(a, a); }
__device__ __forceinline__ u64p pfma(u64p a, u64p b, u64p c) {
    u64p r; asm("fma.rn.f32x2 %0, %1, %2, %3;" : "=l"(r) : "l"(a), "l"(b), "l"(c)); return r;
}
__device__ __forceinline__ u64p pmul(u64p a, u64p b) {
    u64p r; asm("mul.rn.f32x2 %0, %1, %2;" : "=l"(r) : "l"(a), "l"(b)); return r;
}
__device__ __forceinline__ u64p padd(u64p a, u64p b) {
    u64p r; asm("add.rn.f32x2 %0, %1, %2;" : "=l"(r) : "l"(a), "l"(b)); return r;
}

// One complex 4-row: column pairs (0,1) and (2,3), real and imag planes packed
struct PRow { u64p r01, r23, i01, i23; };

// z += (a + ib) * yrow  (complex scalar times complex row, packed over col pairs)
__device__ __forceinline__ void caccum(float a, float b, const PRow& y, PRow& z) {
    u64p sa = psplat(a), sb = psplat(b), snb = psplat(-b);
    z.r01 = pfma(sa, y.r01, pfma(snb, y.i01, z.r01));
    z.r23 = pfma(sa, y.r23, pfma(snb, y.i23, z.r23));
    z.i01 = pfma(sa, y.i01, pfma(sb, y.r01, z.i01));
    z.i23 = pfma(sa, y.i23, pfma(sb, y.r23, z.i23));
}

// z += x * y (4x4 complex, packed). If ZERO, z is initialized first.
template <bool ZERO>
__device__ __forceinline__ void pcmm(const PRow* __restrict__ x, const PRow* __restrict__ y,
                                     PRow* __restrict__ z) {
#pragma unroll
    for (int i = 0; i < 4; ++i) {
        if (ZERO) { z[i].r01 = pk2(0, 0); z[i].r23 = pk2(0, 0); z[i].i01 = pk2(0, 0); z[i].i23 = pk2(0, 0); }
        float er0, er1, er2, er3, ei0, ei1, ei2, ei3;
        upk2(x[i].r01, er0, er1); upk2(x[i].r23, er2, er3);
        upk2(x[i].i01, ei0, ei1); upk2(x[i].i23, ei2, ei3);
        caccum(er0, ei0, y[0], z[i]);
        caccum(er1, ei1, y[1], z[i]);
        caccum(er2, ei2, y[2], z[i]);
        caccum(er3, ei3, y[3], z[i]);
    }
}

// ---------------------------------------------------------------------------
// Scalar helpers (k_chunk / k_scan / k_apply)
__device__ __forceinline__ void cax4(float a, float b, float4 cr, float4 ci,
                                     float4& accr, float4& acci) {
    accr.x = fmaf(a, cr.x, fmaf(-b, ci.x, accr.x));
    acci.x = fmaf(a, ci.x, fmaf( b, cr.x, acci.x));
    accr.y = fmaf(a, cr.y, fmaf(-b, ci.y, accr.y));
    acci.y = fmaf(a, ci.y, fmaf( b, cr.y, acci.y));
    accr.z = fmaf(a, cr.z, fmaf(-b, ci.z, accr.z));
    acci.z = fmaf(a, ci.z, fmaf( b, cr.z, acci.z));
    accr.w = fmaf(a, cr.w, fmaf(-b, ci.w, accr.w));
    acci.w = fmaf(a, ci.w, fmaf( b, cr.w, acci.w));
}

// ---------------------------------------------------------------------------
// K0: U = expm(-i*dt*H), degree-4 Taylor via packed f32x2:
//   E = I + A + A^2 * (I/2 + A/6 + A^2/24)
__global__ void __launch_bounds__(128) k_expm(const float* __restrict__ hr_g,
                                              const float* __restrict__ hi_g) {
    int idx = blockIdx.x * 128 + threadIdx.x;

    const float4* hr4 = reinterpret_cast<const float4*>(hr_g) + (size_t)idx * 4;
    const float4* hi4 = reinterpret_cast<const float4*>(hi_g) + (size_t)idx * 4;

    // A = dt*hi - i*dt*hr
    PRow A[4];
    const u64p pdt = psplat(DT), pndt = psplat(-DT);
#pragma unroll
    for (int i = 0; i < 4; ++i) {
        float4 r = hr4[i], m = hi4[i];
        A[i].r01 = pmul(pdt,  pk2(m.x, m.y));
        A[i].r23 = pmul(pdt,  pk2(m.z, m.w));
        A[i].i01 = pmul(pndt, pk2(r.x, r.y));
        A[i].i23 = pmul(pndt, pk2(r.z, r.w));
    }

    PRow B[4];                   // A^2
    pcmm<true>(A, A, B);

    // M = I/2 + A/6 + A^2/24
    PRow M[4];
    const u64p c6 = psplat(1.0f / 6.0f), c24 = psplat(1.0f / 24.0f);
#pragma unroll
    for (int i = 0; i < 4; ++i) {
        M[i].r01 = pfma(c6, A[i].r01, pmul(c24, B[i].r01));
        M[i].r23 = pfma(c6, A[i].r23, pmul(c24, B[i].r23));
        M[i].i01 = pfma(c6, A[i].i01, pmul(c24, B[i].i01));
        M[i].i23 = pfma(c6, A[i].i23, pmul(c24, B[i].i23));
    }
    M[0].r01 = padd(M[0].r01, pk2(0.5f, 0.0f));
    M[1].r01 = padd(M[1].r01, pk2(0.0f, 0.5f));
    M[2].r23 = padd(M[2].r23, pk2(0.5f, 0.0f));
    M[3].r23 = padd(M[3].r23, pk2(0.0f, 0.5f));

    // E = A + B*M  (accumulate into A), then +I
    pcmm<false>(B, M, A);
    A[0].r01 = padd(A[0].r01, pk2(1.0f, 0.0f));
    A[1].r01 = padd(A[1].r01, pk2(0.0f, 1.0f));
    A[2].r23 = padd(A[2].r23, pk2(1.0f, 0.0f));
    A[3].r23 = padd(A[3].r23, pk2(0.0f, 1.0f));

    // store planar: re[16] then im[16]
    float4* Up = g_U + (size_t)idx * 8;
#pragma unroll
    for (int i = 0; i < 4; ++i) {
        float x0, x1, x2, x3;
        upk2(A[i].r01, x0, x1); upk2(A[i].r23, x2, x3);
        Up[i] = make_float4(x0, x1, x2, x3);
    }
#pragma unroll
    for (int i = 0; i < 4; ++i) {
        float x0, x1, x2, x3;
        upk2(A[i].i01, x0, x1); upk2(A[i].i23, x2, x3);
        Up[4 + i] = make_float4(x0, x1, x2, x3);
    }
}

// ---------------------------------------------------------------------------
// K1: per-column chunk product. Thread = (chunk, column j), U staged in smem.
#define CH_STRIDE4 65

__global__ void __launch_bounds__(128) k_chunk() {
    __shared__ float4 sU[32 * CH_STRIDE4];
    int idx0 = blockIdx.x * 32;
    int tid = threadIdx.x;
#pragma unroll
    for (int k = tid; k < 32 * 64; k += 128) {
        int cl = k >> 6, w = k & 63;
        sU[cl * CH_STRIDE4 + w] = g_U[((size_t)(idx0 + cl)) * 64 + w];
    }
    __syncthreads();

    int cl = tid >> 2, j = tid & 3;
    int idx = idx0 + cl;

    float sr[4] = {0, 0, 0, 0}, si[4] = {0, 0, 0, 0};
    sr[j] = 1.0f;

    const float4* Ub = sU + cl * CH_STRIDE4;
#pragma unroll
    for (int l = 0; l < LL; ++l) {
        float tr[4], ti[4];
#pragma unroll
        for (int i = 0; i < 4; ++i) {
            float4 urv = Ub[l * 8 + i];
            float4 uiv = Ub[l * 8 + 4 + i];
            float xr = 0.0f, xi = 0.0f;
            xr = fmaf(urv.x, sr[0], xr); xr = fmaf(-uiv.x, si[0], xr);
            xi = fmaf(urv.x, si[0], xi); xi = fmaf( uiv.x, sr[0], xi);
            xr = fmaf(urv.y, sr[1], xr); xr = fmaf(-uiv.y, si[1], xr);
            xi = fmaf(urv.y, si[1], xi); xi = fmaf( uiv.y, sr[1], xi);
            xr = fmaf(urv.z, sr[2], xr); xr = fmaf(-uiv.z, si[2], xr);
            xi = fmaf(urv.z, si[2], xi); xi = fmaf( uiv.z, sr[2], xi);
            xr = fmaf(urv.w, sr[3], xr); xr = fmaf(-uiv.w, si[3], xr);
            xi = fmaf(urv.w, si[3], xi); xi = fmaf( uiv.w, sr[3], xi);
            tr[i] = xr; ti[i] = xi;
        }
#pragma unroll
        for (int i = 0; i < 4; ++i) { sr[i] = tr[i]; si[i] = ti[i]; }
    }

    float* Pp = reinterpret_cast<float*>(g_P) + (size_t)idx * 32;
#pragma unroll
    for (int i = 0; i < 4; ++i) { Pp[i * 4 + j] = sr[i]; Pp[16 + i * 4 + j] = si[i]; }
}

// ---------------------------------------------------------------------------
// K2: row-parallel per-batch Kogge-Stone scan. 1024 threads = 256 chunks x 4 rows.
__global__ void __launch_bounds__(1024) k_scan(const float* __restrict__ s0r_g,
                                               const float* __restrict__ s0i_g) {
    __shared__ float4 sh[CC * 12];
    int b = blockIdx.x;
    int tid = threadIdx.x;
    int e = tid >> 2, i = tid & 3;

    const float4* Pg = g_P + ((size_t)b * CC + e) * 8;
    float4 pr = Pg[i];
    float4 pim = Pg[4 + i];

#pragma unroll
    for (int d = 1; d < CC; d <<= 1) {
        sh[e * 12 + i] = pr;
        sh[e * 12 + 4 + i] = pim;
        __syncthreads();
        if (e >= d) {
            const float4* nb = sh + (e - d) * 12;
            float4 l0r = nb[0], l1r = nb[1], l2r = nb[2], l3r = nb[3];
            float4 l0i = nb[4], l1i = nb[5], l2i = nb[6], l3i = nb[7];
            float4 nr = make_float4(0, 0, 0, 0), ni = make_float4(0, 0, 0, 0);
            cax4(pr.x, pim.x, l0r, l0i, nr, ni);
            cax4(pr.y, pim.y, l1r, l1i, nr, ni);
            cax4(pr.z, pim.z, l2r, l2i, nr, ni);
            cax4(pr.w, pim.w, l3r, l3i, nr, ni);
            pr = nr; pim = ni;
        }
        __syncthreads();
    }

    sh[e * 12 + i] = pr;
    sh[e * 12 + 4 + i] = pim;
    __syncthreads();

    const float4* r4 = reinterpret_cast<const float4*>(s0r_g) + (size_t)b * 4;
    const float4* i4 = reinterpret_cast<const float4*>(s0i_g) + (size_t)b * 4;
    float4 s0r0 = r4[0], s0r1 = r4[1], s0r2 = r4[2], s0r3 = r4[3];
    float4 s0i0 = i4[0], s0i1 = i4[1], s0i2 = i4[2], s0i3 = i4[3];

    float4 vr, vi;
    if (e == 0) {
        vr = (i == 0) ? s0r0 : (i == 1) ? s0r1 : (i == 2) ? s0r2 : s0r3;
        vi = (i == 0) ? s0i0 : (i == 1) ? s0i1 : (i == 2) ? s0i2 : s0i3;
    } else {
        float4 qr = sh[(e - 1) * 12 + i];
        float4 qi = sh[(e - 1) * 12 + 4 + i];
        vr = make_float4(0, 0, 0, 0); vi = make_float4(0, 0, 0, 0);
        cax4(qr.x, qi.x, s0r0, s0i0, vr, vi);
        cax4(qr.y, qi.y, s0r1, s0i1, vr, vi);
        cax4(qr.z, qi.z, s0r2, s0i2, vr, vi);
        cax4(qr.w, qi.w, s0r3, s0i3, vr, vi);
    }
    float4* Sg = g_S + ((size_t)b * CC + e) * 8;
    Sg[i] = vr;
    Sg[4 + i] = vi;
}

// ---------------------------------------------------------------------------
// K3: ROW-parallel apply, NO U staging: each thread reads only its own U rows
// directly from g_U (L2-resident) with one-step register prefetch. State in
// smem double-buffered; all sharing is within 4-lane groups => __syncwarp only.
__global__ void __launch_bounds__(128) k_apply(float* __restrict__ out) {
    __shared__ float4 sS[2][32 * 12];        // 12 KB, double-buffered state

    int tid = threadIdx.x;
    int cl = tid >> 2, i = tid & 3;
    int idx = blockIdx.x * 32 + cl;          // = b*CC + c
    int b = idx >> 8;
    int c = idx & (CC - 1);

    {   // stage incoming state rows (coalesced float4 loads)
        const float4* Sg = g_S + (size_t)idx * 8;
        sS[0][cl * 12 + i] = Sg[i];
        sS[0][cl * 12 + 4 + i] = Sg[4 + i];
    }

    const float4* Ug = g_U + (size_t)idx * 64;
    // prefetch U rows for l=0
    float4 ur = Ug[i], ui = Ug[4 + i];

    __syncwarp();

    const size_t imag_off = (size_t)TT * BB * 16;
    float* ob = out + (((size_t)c * LL) * BB + b) * 16 + i * 4;

#pragma unroll
    for (int l = 0; l < LL; ++l) {
        float4 nur, nui;
        if (l < LL - 1) {                    // prefetch next step's U rows
            nur = Ug[(l + 1) * 8 + i];
            nui = Ug[(l + 1) * 8 + 4 + i];
        }

        const int cur = l & 1;
        float4 s0r = sS[cur][cl * 12 + 0];
        float4 s1r = sS[cur][cl * 12 + 1];
        float4 s2r = sS[cur][cl * 12 + 2];
        float4 s3r = sS[cur][cl * 12 + 3];
        float4 s0i = sS[cur][cl * 12 + 4];
        float4 s1i = sS[cur][cl * 12 + 5];
        float4 s2i = sS[cur][cl * 12 + 6];
        float4 s3i = sS[cur][cl * 12 + 7];

        float4 nr = make_float4(0, 0, 0, 0), ni = make_float4(0, 0, 0, 0);
        cax4(ur.x, ui.x, s0r, s0i, nr, ni);
        cax4(ur.y, ui.y, s1r, s1i, nr, ni);
        cax4(ur.z, ui.z, s2r, s2i, nr, ni);
        cax4(ur.w, ui.w, s3r, s3i, nr, ni);

        if (l < LL - 1) {
            sS[cur ^ 1][cl * 12 + i] = nr;
            sS[cur ^ 1][cl * 12 + 4 + i] = ni;
        }

        float* op = ob + (size_t)l * BB * 16;
        *reinterpret_cast<float4*>(op) = nr;
        *reinterpret_cast<float4*>(op + imag_off) = ni;

        __syncwarp();
        ur = nur; ui = nui;
    }
}

// ---------------------------------------------------------------------------
extern "C" void kernel_launch(void* const* d_in, const int* in_sizes, int n_in,
                              void* d_out, int out_size) {
    const float* h_real = (const float*)d_in[0];
    const float* h_imag = (const float*)d_in[1];
    const float* s_real = (const float*)d_in[2];
    const float* s_imag = (const float*)d_in[3];
    float* out = (float*)d_out;

    k_expm<<<NM / 128, 128>>>(h_real, h_imag);
    k_chunk<<<(BB * CC) / 32, 128>>>();
    k_scan<<<BB, CC * 4>>>(s_real, s_imag);
    k_apply<<<(BB * CC) / 32, 128>>>(out);
}

// round 6
// speedup vs baseline: 1.4121x; 1.1484x over previous
#include <cuda_runtime.h>

// Problem constants
#define BB 128
#define TT 2048
#define LL 8              // timesteps per chunk
#define CC (TT / LL)      // 256 chunks per batch
#define NM (BB * TT)      // 262144 matrices total
#define DT 0.02f

// Scratch: 32 floats per 4x4 complex matrix = [re[16], im[16]] = 8 float4 (128B)
__device__ __align__(128) float4 g_U[(size_t)NM * 8];        // 33.5 MB: all unitaries
__device__ __align__(128) float4 g_P[(size_t)BB * CC * 8];   // chunk products
__device__ __align__(128) float4 g_S[(size_t)BB * CC * 8];   // incoming state per chunk

// ---------------------------------------------------------------------------
// Packed f32x2 primitives (FFMA2 — only reachable via PTX)
typedef unsigned long long u64p;

__device__ __forceinline__ u64p pk2(float x, float y) {
    u64p r; asm("mov.b64 %0, {%1, %2};" : "=l"(r) : "f"(x), "f"(y)); return r;
}
__device__ __forceinline__ void upk2(u64p v, float& x, float& y) {
    asm("mov.b64 {%0, %1}, %2;" : "=f"(x), "=f"(y) : "l"(v));
}
__device__ __forceinline__ u64p psplat(float a) { return pk2(a, a); }
__device__ __forceinline__ u64p pfma(u64p a, u64p b, u64p c) {
    u64p r; asm("fma.rn.f32x2 %0, %1, %2, %3;" : "=l"(r) : "l"(a), "l"(b), "l"(c)); return r;
}
__device__ __forceinline__ u64p pmul(u64p a, u64p b) {
    u64p r; asm("mul.rn.f32x2 %0, %1, %2;" : "=l"(r) : "l"(a), "l"(b)); return r;
}
__device__ __forceinline__ u64p padd(u64p a, u64p b) {
    u64p r; asm("add.rn.f32x2 %0, %1, %2;" : "=l"(r) : "l"(a), "l"(b)); return r;
}

struct PRow { u64p r01, r23, i01, i23; };

__device__ __forceinline__ void caccum(float a, float b, const PRow& y, PRow& z) {
    u64p sa = psplat(a), sb = psplat(b), snb = psplat(-b);
    z.r01 = pfma(sa, y.r01, pfma(snb, y.i01, z.r01));
    z.r23 = pfma(sa, y.r23, pfma(snb, y.i23, z.r23));
    z.i01 = pfma(sa, y.i01, pfma(sb, y.r01, z.i01));
    z.i23 = pfma(sa, y.i23, pfma(sb, y.r23, z.i23));
}

template <bool ZERO>
__device__ __forceinline__ void pcmm(const PRow* __restrict__ x, const PRow* __restrict__ y,
                                     PRow* __restrict__ z) {
#pragma unroll
    for (int i = 0; i < 4; ++i) {
        if (ZERO) { z[i].r01 = pk2(0, 0); z[i].r23 = pk2(0, 0); z[i].i01 = pk2(0, 0); z[i].i23 = pk2(0, 0); }
        float er0, er1, er2, er3, ei0, ei1, ei2, ei3;
        upk2(x[i].r01, er0, er1); upk2(x[i].r23, er2, er3);
        upk2(x[i].i01, ei0, ei1); upk2(x[i].i23, ei2, ei3);
        caccum(er0, ei0, y[0], z[i]);
        caccum(er1, ei1, y[1], z[i]);
        caccum(er2, ei2, y[2], z[i]);
        caccum(er3, ei3, y[3], z[i]);
    }
}

// ---------------------------------------------------------------------------
// Scalar helpers
__device__ __forceinline__ void cax4(float a, float b, float4 cr, float4 ci,
                                     float4& accr, float4& acci) {
    accr.x = fmaf(a, cr.x, fmaf(-b, ci.x, accr.x));
    acci.x = fmaf(a, ci.x, fmaf( b, cr.x, acci.x));
    accr.y = fmaf(a, cr.y, fmaf(-b, ci.y, accr.y));
    acci.y = fmaf(a, ci.y, fmaf( b, cr.y, acci.y));
    accr.z = fmaf(a, cr.z, fmaf(-b, ci.z, accr.z));
    acci.z = fmaf(a, ci.z, fmaf( b, cr.z, acci.z));
    accr.w = fmaf(a, cr.w, fmaf(-b, ci.w, accr.w));
    acci.w = fmaf(a, ci.w, fmaf( b, cr.w, acci.w));
}

// row (ur,ui) dot column (sr,si) -> (or_, oi_)
__device__ __forceinline__ void rowdot(float4 ur, float4 ui, const float* __restrict__ sr,
                                       const float* __restrict__ si, float& or_, float& oi_) {
    float xr = 0.0f, xi = 0.0f;
    xr = fmaf(ur.x, sr[0], fmaf(-ui.x, si[0], xr)); xi = fmaf(ur.x, si[0], fmaf(ui.x, sr[0], xi));
    xr = fmaf(ur.y, sr[1], fmaf(-ui.y, si[1], xr)); xi = fmaf(ur.y, si[1], fmaf(ui.y, sr[1], xi));
    xr = fmaf(ur.z, sr[2], fmaf(-ui.z, si[2], xr)); xi = fmaf(ur.z, si[2], fmaf(ui.z, sr[2], xi));
    xr = fmaf(ur.w, sr[3], fmaf(-ui.w, si[3], xr)); xi = fmaf(ur.w, si[3], fmaf(ui.w, sr[3], xi));
    or_ = xr; oi_ = xi;
}

// ---------------------------------------------------------------------------
// K0: U = expm(-i*dt*H), degree-4 Taylor via packed f32x2, with FUSED
// column-parallel chunk product tail (64 threads = 16 chunks x 4 cols).
// smem U copy: chunk cl stride 65 quads; quad q of matrix l stored at
// cl*65 + l*8 + (q^l)  -> stores and tail reads both bank-conflict-free.
__global__ void __launch_bounds__(128) k_expm(const float* __restrict__ hr_g,
                                              const float* __restrict__ hi_g) {
    __shared__ float4 sUc[16 * 65];          // 16,640 B

    int tid = threadIdx.x;
    int idx = blockIdx.x * 128 + tid;

    const float4* hr4 = reinterpret_cast<const float4*>(hr_g) + (size_t)idx * 4;
    const float4* hi4 = reinterpret_cast<const float4*>(hi_g) + (size_t)idx * 4;

    // A = dt*hi - i*dt*hr
    PRow A[4];
    const u64p pdt = psplat(DT), pndt = psplat(-DT);
#pragma unroll
    for (int i = 0; i < 4; ++i) {
        float4 r = hr4[i], m = hi4[i];
        A[i].r01 = pmul(pdt,  pk2(m.x, m.y));
        A[i].r23 = pmul(pdt,  pk2(m.z, m.w));
        A[i].i01 = pmul(pndt, pk2(r.x, r.y));
        A[i].i23 = pmul(pndt, pk2(r.z, r.w));
    }

    PRow B[4];                   // A^2
    pcmm<true>(A, A, B);

    // M = I/2 + A/6 + A^2/24
    PRow M[4];
    const u64p c6 = psplat(1.0f / 6.0f), c24 = psplat(1.0f / 24.0f);
#pragma unroll
    for (int i = 0; i < 4; ++i) {
        M[i].r01 = pfma(c6, A[i].r01, pmul(c24, B[i].r01));
        M[i].r23 = pfma(c6, A[i].r23, pmul(c24, B[i].r23));
        M[i].i01 = pfma(c6, A[i].i01, pmul(c24, B[i].i01));
        M[i].i23 = pfma(c6, A[i].i23, pmul(c24, B[i].i23));
    }
    M[0].r01 = padd(M[0].r01, pk2(0.5f, 0.0f));
    M[1].r01 = padd(M[1].r01, pk2(0.0f, 0.5f));
    M[2].r23 = padd(M[2].r23, pk2(0.5f, 0.0f));
    M[3].r23 = padd(M[3].r23, pk2(0.0f, 0.5f));

    // E = A + B*M  (into A), then +I
    pcmm<false>(B, M, A);
    A[0].r01 = padd(A[0].r01, pk2(1.0f, 0.0f));
    A[1].r01 = padd(A[1].r01, pk2(0.0f, 1.0f));
    A[2].r23 = padd(A[2].r23, pk2(1.0f, 0.0f));
    A[3].r23 = padd(A[3].r23, pk2(0.0f, 1.0f));

    // Unpack to float4 quads; store to global AND smem (swizzled)
    float4 q[8];
#pragma unroll
    for (int i = 0; i < 4; ++i) {
        float x0, x1, x2, x3, y0, y1, y2, y3;
        upk2(A[i].r01, x0, x1); upk2(A[i].r23, x2, x3);
        upk2(A[i].i01, y0, y1); upk2(A[i].i23, y2, y3);
        q[i]     = make_float4(x0, x1, x2, x3);
        q[4 + i] = make_float4(y0, y1, y2, y3);
    }
    float4* Up = g_U + (size_t)idx * 8;
    int cl = tid >> 3, l = tid & 7;
    float4* Sp = sUc + cl * 65 + l * 8;
#pragma unroll
    for (int k = 0; k < 8; ++k) {
        Up[k] = q[k];
        Sp[k ^ l] = q[k];
    }
    __syncthreads();

    // ---- column-parallel chunk product: 64 threads = 16 chunks x 4 cols
    if (tid < 64) {
        int cl2 = tid >> 2, j = tid & 3;
        int chunk = blockIdx.x * 16 + cl2;

        float sr[4] = {0, 0, 0, 0}, si[4] = {0, 0, 0, 0};
        sr[j] = 1.0f;

        const float4* Ub = sUc + cl2 * 65;
#pragma unroll
        for (int l2 = 0; l2 < LL; ++l2) {
            const float4* Um = Ub + l2 * 8;
            float4 u0r = Um[0 ^ l2], u1r = Um[1 ^ l2], u2r = Um[2 ^ l2], u3r = Um[3 ^ l2];
            float4 u0i = Um[4 ^ l2], u1i = Um[5 ^ l2], u2i = Um[6 ^ l2], u3i = Um[7 ^ l2];
            float tr[4], ti[4];
            rowdot(u0r, u0i, sr, si, tr[0], ti[0]);
            rowdot(u1r, u1i, sr, si, tr[1], ti[1]);
            rowdot(u2r, u2i, sr, si, tr[2], ti[2]);
            rowdot(u3r, u3i, sr, si, tr[3], ti[3]);
#pragma unroll
            for (int i = 0; i < 4; ++i) { sr[i] = tr[i]; si[i] = ti[i]; }
        }

        float* Pp = reinterpret_cast<float*>(g_P) + (size_t)chunk * 32;
#pragma unroll
        for (int i = 0; i < 4; ++i) { Pp[i * 4 + j] = sr[i]; Pp[16 + i * 4 + j] = si[i]; }
    }
}

// ---------------------------------------------------------------------------
// K2: row-parallel per-batch Kogge-Stone scan, XOR-swizzled smem (stride 12
// keeps 48KB static limit; index k^(e&7) makes residues 4e+(k^e) all-distinct).
__global__ void __launch_bounds__(1024) k_scan(const float* __restrict__ s0r_g,
                                               const float* __restrict__ s0i_g) {
    __shared__ float4 sh[CC * 12];
    int b = blockIdx.x;
    int tid = threadIdx.x;
    int e = tid >> 2, i = tid & 3;
    int es = e & 7;

    const float4* Pg = g_P + ((size_t)b * CC + e) * 8;
    float4 pr = Pg[i];
    float4 pim = Pg[4 + i];

#pragma unroll
    for (int d = 1; d < CC; d <<= 1) {
        float4* me = sh + e * 12;
        me[i ^ es] = pr;
        me[(4 + i) ^ es] = pim;
        __syncthreads();
        if (e >= d) {
            int ens = (e - d) & 7;
            const float4* nb = sh + (e - d) * 12;
            float4 l0r = nb[0 ^ ens], l1r = nb[1 ^ ens], l2r = nb[2 ^ ens], l3r = nb[3 ^ ens];
            float4 l0i = nb[4 ^ ens], l1i = nb[5 ^ ens], l2i = nb[6 ^ ens], l3i = nb[7 ^ ens];
            float4 nr = make_float4(0, 0, 0, 0), ni = make_float4(0, 0, 0, 0);
            cax4(pr.x, pim.x, l0r, l0i, nr, ni);
            cax4(pr.y, pim.y, l1r, l1i, nr, ni);
            cax4(pr.z, pim.z, l2r, l2i, nr, ni);
            cax4(pr.w, pim.w, l3r, l3i, nr, ni);
            pr = nr; pim = ni;
        }
        __syncthreads();
    }

    {
        float4* me = sh + e * 12;
        me[i ^ es] = pr;
        me[(4 + i) ^ es] = pim;
    }
    __syncthreads();

    const float4* r4 = reinterpret_cast<const float4*>(s0r_g) + (size_t)b * 4;
    const float4* i4 = reinterpret_cast<const float4*>(s0i_g) + (size_t)b * 4;
    float4 s0r0 = r4[0], s0r1 = r4[1], s0r2 = r4[2], s0r3 = r4[3];
    float4 s0i0 = i4[0], s0i1 = i4[1], s0i2 = i4[2], s0i3 = i4[3];

    float4 vr, vi;
    if (e == 0) {
        vr = (i == 0) ? s0r0 : (i == 1) ? s0r1 : (i == 2) ? s0r2 : s0r3;
        vi = (i == 0) ? s0i0 : (i == 1) ? s0i1 : (i == 2) ? s0i2 : s0i3;
    } else {
        int ens = (e - 1) & 7;
        const float4* nb = sh + (e - 1) * 12;
        float4 qr = nb[i ^ ens];
        float4 qi = nb[(4 + i) ^ ens];
        vr = make_float4(0, 0, 0, 0); vi = make_float4(0, 0, 0, 0);
        cax4(qr.x, qi.x, s0r0, s0i0, vr, vi);
        cax4(qr.y, qi.y, s0r1, s0i1, vr, vi);
        cax4(qr.z, qi.z, s0r2, s0i2, vr, vi);
        cax4(qr.w, qi.w, s0r3, s0i3, vr, vi);
    }
    float4* Sg = g_S + ((size_t)b * CC + e) * 8;
    Sg[i] = vr;
    Sg[4 + i] = vi;
}

// ---------------------------------------------------------------------------
// K3: ROW-parallel apply, BATCH-MAJOR mapping: warp's 8 chunk-groups are 8
// consecutive b with the same c -> each STG.128 writes 512B contiguous.
// State in smem double-buffered, stride 13 (conflict-free: 5cl mod 8 distinct).
#define SSTR 13

__global__ void __launch_bounds__(128) k_apply(float* __restrict__ out) {
    __shared__ float4 sS[2][32 * SSTR];      // 13,312 B

    int tid = threadIdx.x;
    int cl = tid >> 2, i = tid & 3;
    int gidx = blockIdx.x * 32 + cl;         // b-fast ordering
    int b = gidx & (BB - 1);
    int c = gidx >> 7;                       // / BB
    int idx = b * CC + c;                    // chunk index in g_U/g_S

    {   // stage incoming state rows
        const float4* Sg = g_S + (size_t)idx * 8;
        sS[0][cl * SSTR + i] = Sg[i];
        sS[0][cl * SSTR + 4 + i] = Sg[4 + i];
    }

    const float4* Ug = g_U + (size_t)idx * 64;
    float4 ur = Ug[i], ui = Ug[4 + i];       // prefetch l=0

    __syncwarp();

    const size_t imag_off = (size_t)TT * BB * 16;
    float* ob = out + (((size_t)c * LL) * BB + b) * 16 + i * 4;

#pragma unroll
    for (int l = 0; l < LL; ++l) {
        float4 nur, nui;
        if (l < LL - 1) {
            nur = Ug[(l + 1) * 8 + i];
            nui = Ug[(l + 1) * 8 + 4 + i];
        }

        const int cur = l & 1;
        float4 s0r = sS[cur][cl * SSTR + 0];
        float4 s1r = sS[cur][cl * SSTR + 1];
        float4 s2r = sS[cur][cl * SSTR + 2];
        float4 s3r = sS[cur][cl * SSTR + 3];
        float4 s0i = sS[cur][cl * SSTR + 4];
        float4 s1i = sS[cur][cl * SSTR + 5];
        float4 s2i = sS[cur][cl * SSTR + 6];
        float4 s3i = sS[cur][cl * SSTR + 7];

        float4 nr = make_float4(0, 0, 0, 0), ni = make_float4(0, 0, 0, 0);
        cax4(ur.x, ui.x, s0r, s0i, nr, ni);
        cax4(ur.y, ui.y, s1r, s1i, nr, ni);
        cax4(ur.z, ui.z, s2r, s2i, nr, ni);
        cax4(ur.w, ui.w, s3r, s3i, nr, ni);

        if (l < LL - 1) {
            sS[cur ^ 1][cl * SSTR + i] = nr;
            sS[cur ^ 1][cl * SSTR + 4 + i] = ni;
        }

        float* op = ob + (size_t)l * BB * 16;
        __stcs(reinterpret_cast<float4*>(op), nr);
        __stcs(reinterpret_cast<float4*>(op + imag_off), ni);

        __syncwarp();
        ur = nur; ui = nui;
    }
}

// ---------------------------------------------------------------------------
extern "C" void kernel_launch(void* const* d_in, const int* in_sizes, int n_in,
                              void* d_out, int out_size) {
    const float* h_real = (const float*)d_in[0];
    const float* h_imag = (const float*)d_in[1];
    const float* s_real = (const float*)d_in[2];
    const float* s_imag = (const float*)d_in[3];
    float* out = (float*)d_out;

    k_expm<<<NM / 128, 128>>>(h_real, h_imag);
    k_scan<<<BB, CC * 4>>>(s_real, s_imag);
    k_apply<<<(BB * CC) / 32, 128>>>(out);
}